// round 17
// baseline (speedup 1.0000x reference)
#include <cuda_runtime.h>
#include <cuda_bf16.h>
#include <cstdint>

#define B_ 128
#define G_ 512
#define H_ 128

static __device__ __constant__ float kAlphaHalf = 0.05f;   // ALPHA * 0.5

// ---------------- scratch (static device globals; no allocation) -------------
__device__ float    g_buf[B_ * H_];        // g (B,H) fp32
__device__ uint8_t  xq_buf[B_ * G_];       // baseline in e4m3, scaled by 16
__device__ float    corr_buf[B_ * G_];     // Sum_h g*S (descaled), layout [b][i]
__device__ float    bx_buf[B_ * G_];       // Sum_j b2[jG+i] x[b,j], [b][i]

#define XS 16.0f          // X fp8 scale
#define WS 4096.0f        // W fp8 scale
#define INV_S (1.0f / (XS * WS))

__device__ __forceinline__ float dot4(float4 a, float4 b) {
    return a.x * b.x + a.y * b.y + a.z * b.z + a.w * b.w;
}
template <int U>
__device__ __forceinline__ void wredN(float* a) {
    #pragma unroll
    for (int d = 16; d; d >>= 1)
        #pragma unroll
        for (int u = 0; u < U; u++)
            a[u] += __shfl_xor_sync(0xffffffffu, a[u], d);
}

// ============================================================================
// K1: encoders -> g, plus e4m3 copy of baseline (x*16). One CTA per sample b.
// ============================================================================
__global__ __launch_bounds__(1024) void k1_encode(
    const int*   __restrict__ pert,
    const float* __restrict__ x,
    const float* __restrict__ embW,
    const float* __restrict__ geW1, const float* __restrict__ geb1,
    const float* __restrict__ geW2, const float* __restrict__ geb2,
    const float* __restrict__ grnW1, const float* __restrict__ grnb1)
{
    __shared__ __align__(16) float sx[G_];
    __shared__ __align__(16) float sh[H_];
    __shared__ __align__(16) float sc[2 * H_];
    const int b = blockIdx.x, t = threadIdx.x;
    const int lane = t & 31, w = t >> 5;
    const float* xr = x + b * G_;

    if (t < G_) {
        float v = xr[t];
        sx[t] = v;
        uint16_t q;
        asm("cvt.rn.satfinite.e4m3x2.f32 %0, %1, %2;"
            : "=h"(q) : "f"(0.f), "f"(v * XS));
        xq_buf[b * G_ + t] = (uint8_t)q;
    }
    if (t < H_) sc[t] = embW[pert[b] * H_ + t];
    __syncthreads();

    {
        const float4* sx4 = (const float4*)sx;
        float4 xv[4];
        #pragma unroll
        for (int k = 0; k < 4; k++) xv[k] = sx4[lane + 32 * k];
        const int h = w * 4;
        float a[4];
        #pragma unroll
        for (int u = 0; u < 4; u++) {
            const float4* wp = (const float4*)(geW1 + (h + u) * G_);
            float s = 0.f;
            #pragma unroll
            for (int k = 0; k < 4; k++) s += dot4(wp[lane + 32 * k], xv[k]);
            a[u] = s;
        }
        wredN<4>(a);
        if (lane == 0) {
            #pragma unroll
            for (int u = 0; u < 4; u++)
                sh[h + u] = fmaxf(a[u] + geb1[h + u], 0.f);
        }
    }
    __syncthreads();

    {
        const float4* sh4 = (const float4*)sh;
        float4 hv = sh4[lane];
        const int h = w * 4;
        float a[4];
        #pragma unroll
        for (int u = 0; u < 4; u++)
            a[u] = dot4(((const float4*)(geW2 + (h + u) * H_))[lane], hv);
        wredN<4>(a);
        if (lane == 0) {
            #pragma unroll
            for (int u = 0; u < 4; u++)
                sc[H_ + h + u] = fmaxf(a[u] + geb2[h + u], 0.f);
        }
    }
    __syncthreads();

    {
        const float4* sc4 = (const float4*)sc;
        float4 cv0 = sc4[lane], cv1 = sc4[lane + 32];
        const int h = w * 4;
        float a[4];
        #pragma unroll
        for (int u = 0; u < 4; u++) {
            const float4* wp = (const float4*)(grnW1 + (h + u) * 2 * H_);
            a[u] = dot4(wp[lane], cv0) + dot4(wp[lane + 32], cv1);
        }
        wredN<4>(a);
        if (lane == 0) {
            #pragma unroll
            for (int u = 0; u < 4; u++)
                g_buf[b * H_ + h + u] = fmaxf(a[u] + grnb1[h + u], 0.f);
        }
    }
}

// ============================================================================
// K3 (+ folded K2): blocks [0,512) big GEMM+epilogue (FP8 e4m3 mma.m16n8k32);
// blocks [512,576) compute bx_buf = X @ B2.
//   C[b,h] = Sum_j Xq[b,j] * W2q[(j*G+i)*H+h]  (scaled e4m3)
//   corr[b,i] = (Sum_h C[b,h] * g[b,h]) / (XS*WS)
// W2: coalesced LDG.128 regs (1 chunk ahead) -> scale+cvt e4m3 -> STS [h][j].
// A (X): cp.async fp8 tiles (PITCH 48 = 16B-aligned), ldmatrix reinterpretation.
// ============================================================================
__device__ __forceinline__ void ldsm_x4(uint32_t addr, uint32_t& r0, uint32_t& r1,
                                        uint32_t& r2, uint32_t& r3) {
    asm volatile("ldmatrix.sync.aligned.m8n8.x4.shared.b16 {%0,%1,%2,%3},[%4];"
                 : "=r"(r0), "=r"(r1), "=r"(r2), "=r"(r3) : "r"(addr));
}
__device__ __forceinline__ void cp16(void* dst, const void* src) {
    uint32_t d = (uint32_t)__cvta_generic_to_shared(dst);
    asm volatile("cp.async.cg.shared.global [%0],[%1],16;\n" :: "r"(d), "l"(src));
}
#define MMA16832(d, a, b0r, b1r)                                            \
    asm volatile(                                                           \
        "mma.sync.aligned.m16n8k32.row.col.f32.e4m3.e4m3.f32 "              \
        "{%0,%1,%2,%3},{%4,%5,%6,%7},{%8,%9},{%0,%1,%2,%3};"                \
        : "+f"((d)[0]), "+f"((d)[1]), "+f"((d)[2]), "+f"((d)[3])            \
        : "r"((a)[0]), "r"((a)[1]), "r"((a)[2]), "r"((a)[3]),               \
          "r"(b0r), "r"(b1r))

#define K3_CH   32          // j per chunk (= one k32 MMA step)
#define K3_NCH  16
#define K3_PA   48          // A tile pitch BYTES (32B row + 16 pad; 16B-aligned)
#define K3_PB   36          // B tile pitch bytes ([h][j] rows; 4B-aligned use only)
// dynamic smem layout (bytes)
#define K3_SA_OFF   0                       // 4 * 128*48 = 24576
#define K3_SB_OFF   24576                   // 2 * 128*36 =  9216
#define K3_PRED_OFF 33792                   // 128*8*4    =  4096
#define K3_SMEM     40960                   // (folded-K2 path needs 40960)

__global__ __launch_bounds__(256, 2) void k3_main(
    const float* __restrict__ W2,
    const float* __restrict__ x,
    const float* __restrict__ b2)
{
    extern __shared__ char smem[];
    const int t = threadIdx.x;

    // ---------------- folded K2: bx_buf = X @ B2 ----------------------------
    if (blockIdx.x >= G_) {
        float* sX = (float*)smem;                                // [16][512]
        float (*sB2)[64] = (float (*)[64])(smem + 16 * G_ * 4);  // [32][64]
        const int blk = blockIdx.x - G_;
        const int bc = blk >> 3, ic = blk & 7;
        const int b0 = bc * 16, i0 = ic * 64;
        const int i_loc = t & 63, bgrp = t >> 6;

        for (int idx = t; idx < 16 * 128; idx += 256) {
            const int r = idx >> 7, c4 = idx & 127;
            ((float4*)(sX + r * G_))[c4] = *(const float4*)(x + (b0 + r) * G_ + c4 * 4);
        }
        float acc[4] = {0.f, 0.f, 0.f, 0.f};
        for (int jc = 0; jc < 16; jc++) {
            __syncthreads();
            for (int idx = t; idx < 32 * 16; idx += 256) {
                const int r = idx >> 4, q = idx & 15;
                ((float4*)sB2[r])[q] = *(const float4*)(b2 + (jc * 32 + r) * G_ + i0 + q * 4);
            }
            __syncthreads();
            #pragma unroll 8
            for (int j = 0; j < 32; j++) {
                const float bv = sB2[j][i_loc];
                #pragma unroll
                for (int r = 0; r < 4; r++)
                    acc[r] += bv * sX[(bgrp * 4 + r) * G_ + jc * 32 + j];
            }
        }
        #pragma unroll
        for (int r = 0; r < 4; r++)
            bx_buf[(b0 + bgrp * 4 + r) * G_ + i0 + i_loc] = acc[r];
        return;
    }

    // ---------------- main GEMM path (FP8) ----------------------------------
    char* sA = smem + K3_SA_OFF;            // [4][128*48] e4m3
    char* sB = smem + K3_SB_OFF;            // [2][128*36] e4m3, rows = h
    float (*pred)[8] = (float (*)[8])(smem + K3_PRED_OFF);  // [128][8]

    const int i_cta = blockIdx.x;
    const int lane = t & 31, w = t >> 5;
    const int wm = w & 3, wn = w >> 2;
    const long rowstride = (long)G_ * H_;   // floats between adjacent j rows

    float acc[2][8][4];
    #pragma unroll
    for (int mt = 0; mt < 2; mt++)
        #pragma unroll
        for (int nt = 0; nt < 8; nt++)
            #pragma unroll
            for (int r = 0; r < 4; r++) acc[mt][nt][r] = 0.f;

    // W2 regs: warp w owns rows w*4..+3; thread cols lane*4..+3 (coalesced)
    float rw[4][4];
    auto ldgW = [&](int c) {
        if (c >= K3_NCH) return;
        const float* base = W2 + ((long)(c * K3_CH + w * 4) * G_ + i_cta) * H_
                            + lane * 4;
        #pragma unroll
        for (int k = 0; k < 4; k++) {
            float4 v = __ldg((const float4*)(base + k * rowstride));
            rw[k][0] = v.x; rw[k][1] = v.y; rw[k][2] = v.z; rw[k][3] = v.w;
        }
    };
    auto pfW = [&](int c) {
        if (c >= K3_NCH) return;
        const float* base = W2 + ((long)(c * K3_CH + w * 4) * G_ + i_cta) * H_
                            + lane * 4;
        #pragma unroll
        for (int k = 0; k < 4; k++)
            asm volatile("prefetch.global.L2 [%0];" :: "l"(base + k * rowstride));
    };

    // A tile: 128 b-rows x 32 j-bytes (e4m3), pitch 48; 1 cp16 per thread
    auto issueA = [&](int c) {
        if (c >= K3_NCH) return;
        char* sAb = sA + (c & 3) * 128 * K3_PA;
        const int j0 = c * K3_CH;
        const int r = t >> 1, seg = t & 1;
        cp16(sAb + r * K3_PA + seg * 16, &xq_buf[r * G_ + j0 + seg * 16]);
        asm volatile("cp.async.commit_group;\n" ::: "memory");
    };

    ldgW(0);
    pfW(1);
    issueA(0); issueA(1); issueA(2);
    for (int c = 0; c < K3_NCH; c++) {
        // convert OWN regs (chunk c): scale*cvt -> [h][j] word STS.
        // sB[c&1] last read by MMA(c-2), done by all before iter-(c-1) barrier.
        {
            char* sBb = sB + (c & 1) * 128 * K3_PB;
            #pragma unroll
            for (int u = 0; u < 4; u++) {
                uint16_t lo, hi;
                asm("cvt.rn.satfinite.e4m3x2.f32 %0, %1, %2;"
                    : "=h"(lo) : "f"(rw[1][u] * WS), "f"(rw[0][u] * WS));
                asm("cvt.rn.satfinite.e4m3x2.f32 %0, %1, %2;"
                    : "=h"(hi) : "f"(rw[3][u] * WS), "f"(rw[2][u] * WS));
                uint32_t word = (uint32_t)lo | ((uint32_t)hi << 16);
                *(uint32_t*)(sBb + (lane * 4 + u) * K3_PB + w * 4) = word;
            }
        }
        ldgW(c + 1);
        pfW(c + 2);

        if (c < K3_NCH - 2)
            asm volatile("cp.async.wait_group 2;\n" ::: "memory");
        else if (c == K3_NCH - 2)
            asm volatile("cp.async.wait_group 1;\n" ::: "memory");
        else
            asm volatile("cp.async.wait_group 0;\n" ::: "memory");
        __syncthreads();   // sole barrier: STS + cp.async(c) visible to all

        const char* sAc = sA + (c & 3) * 128 * K3_PA;
        const char* sBc = sB + (c & 1) * 128 * K3_PB;

        // A fragments: 2 m-tiles, whole k32 (byte-identical to bf16 k16 frag)
        uint32_t afr[2][4];
        #pragma unroll
        for (int mt = 0; mt < 2; mt++) {
            const int row = wm * 32 + mt * 16 + (lane & 15);
            uint32_t a = (uint32_t)__cvta_generic_to_shared(
                sAc + row * K3_PA + (lane >> 4) * 16);
            ldsm_x4(a, afr[mt][0], afr[mt][1], afr[mt][2], afr[mt][3]);
        }
        // B fragments: [h][j] rows; thread t: n-row = base + t/4, k-bytes (t%4)*4
        uint32_t bfr[8][2];
        #pragma unroll
        for (int nt = 0; nt < 8; nt++) {
            const int hrow = wn * 64 + nt * 8 + (lane >> 2);
            const char* p = sBc + hrow * K3_PB + (lane & 3) * 4;
            bfr[nt][0] = *(const uint32_t*)(p);
            bfr[nt][1] = *(const uint32_t*)(p + 16);
        }
        #pragma unroll
        for (int mt = 0; mt < 2; mt++)
            #pragma unroll
            for (int nt = 0; nt < 8; nt++)
                MMA16832(acc[mt][nt], afr[mt], bfr[nt][0], bfr[nt][1]);

        issueA(c + 3);     // sA[(c+3)&3] last read in MMA(c-1): done by all
    }

    // epilogue: corr[b,i_cta] = (Sum_h C[b,h]*g[b,h]) * INV_S
    const int rg = lane >> 2, tig = lane & 3;
    #pragma unroll
    for (int mt = 0; mt < 2; mt++) {
        float p0 = 0.f, p1 = 0.f;
        const int brow = wm * 32 + mt * 16 + rg;
        #pragma unroll
        for (int nt = 0; nt < 8; nt++) {
            const int h0 = wn * 64 + nt * 8 + tig * 2;
            float g0 = __ldg(&g_buf[brow * H_ + h0]);
            float g1 = __ldg(&g_buf[brow * H_ + h0 + 1]);
            float g2 = __ldg(&g_buf[(brow + 8) * H_ + h0]);
            float g3 = __ldg(&g_buf[(brow + 8) * H_ + h0 + 1]);
            p0 += acc[mt][nt][0] * g0 + acc[mt][nt][1] * g1;
            p1 += acc[mt][nt][2] * g2 + acc[mt][nt][3] * g3;
        }
        pred[brow][wn * 4 + tig]     = p0;
        pred[brow + 8][wn * 4 + tig] = p1;
    }
    __syncthreads();
    if (t < 128) {
        float s = 0.f;
        #pragma unroll
        for (int cc = 0; cc < 8; cc++) s += pred[t][cc];
        corr_buf[t * G_ + i_cta] = s * INV_S;   // [b][i] layout, descaled
    }
}

// ============================================================================
// K4: y = x/c + (alpha/2)*(corr + Bx)/c^2 ; decoder ; residual. CTA per b.
// ============================================================================
__global__ __launch_bounds__(1024) void k4_dec(
    const float* __restrict__ x,
    const float* __restrict__ dW1, const float* __restrict__ db1,
    const float* __restrict__ dW2, const float* __restrict__ db2,
    float* __restrict__ out)
{
    __shared__ __align__(16) float sx[G_];
    __shared__ __align__(16) float sy[G_];
    __shared__ __align__(16) float sd[H_];
    const int b = blockIdx.x, t = threadIdx.x;
    const int lane = t & 31, w = t >> 5;
    const float cinv = 1.0f / (1.0f + 1e-6f);
    const float scale = kAlphaHalf * cinv * cinv;

    if (t < G_) {
        const float xv = x[b * G_ + t];
        sx[t] = xv;
        const float corr = corr_buf[b * G_ + t] + bx_buf[b * G_ + t];
        sy[t] = xv * cinv + corr * scale;
    }
    __syncthreads();

    {
        const float4* sy4 = (const float4*)sy;
        float4 yv[4];
        #pragma unroll
        for (int k = 0; k < 4; k++) yv[k] = sy4[lane + 32 * k];
        const int h = w * 4;
        float a[4];
        #pragma unroll
        for (int u = 0; u < 4; u++) {
            const float4* wp = (const float4*)(dW1 + (h + u) * G_);
            float s = 0.f;
            #pragma unroll
            for (int k = 0; k < 4; k++) s += dot4(wp[lane + 32 * k], yv[k]);
            a[u] = s;
        }
        wredN<4>(a);
        if (lane == 0) {
            #pragma unroll
            for (int u = 0; u < 4; u++)
                sd[h + u] = fmaxf(a[u] + db1[h + u], 0.f);
        }
    }
    __syncthreads();

    {
        const float4* sd4 = (const float4*)sd;
        float4 dv = sd4[lane];
        #pragma unroll
        for (int og = 0; og < 2; og++) {
            const int i = w * 16 + og * 8;
            float a[8];
            #pragma unroll
            for (int u = 0; u < 8; u++)
                a[u] = dot4(((const float4*)(dW2 + (i + u) * H_))[lane], dv);
            wredN<8>(a);
            if (lane == 0) {
                #pragma unroll
                for (int u = 0; u < 8; u++)
                    out[b * G_ + i + u] = sx[i + u] + db2[i + u] + a[u];
            }
        }
    }
}

// ============================================================================
extern "C" void kernel_launch(void* const* d_in, const int* in_sizes, int n_in,
                              void* d_out, int out_size)
{
    (void)in_sizes; (void)n_in; (void)out_size;
    const int*   pert  = (const int*)  d_in[0];
    const float* x     = (const float*)d_in[1];
    const float* embW  = (const float*)d_in[2];
    const float* geW1  = (const float*)d_in[3];
    const float* geb1  = (const float*)d_in[4];
    const float* geW2  = (const float*)d_in[5];
    const float* geb2  = (const float*)d_in[6];
    const float* grnW1 = (const float*)d_in[7];
    const float* grnb1 = (const float*)d_in[8];
    const float* grnW2 = (const float*)d_in[9];
    const float* grnb2 = (const float*)d_in[10];
    const float* dW1   = (const float*)d_in[11];
    const float* db1   = (const float*)d_in[12];
    const float* dW2   = (const float*)d_in[13];
    const float* db2   = (const float*)d_in[14];
    float* out = (float*)d_out;

    cudaFuncSetAttribute(k3_main, cudaFuncAttributeMaxDynamicSharedMemorySize,
                         K3_SMEM);

    k1_encode<<<B_, 1024>>>(pert, x, embW, geW1, geb1, geW2, geb2, grnW1, grnb1);
    k3_main<<<G_ + 64, 256, K3_SMEM>>>(grnW2, x, grnb2);
    k4_dec<<<B_, 1024>>>(x, dW1, db1, dW2, db2, out);
}